// round 5
// baseline (speedup 1.0000x reference)
#include <cuda_runtime.h>
#include <math.h>
#include <stdint.h>

#define BB     512
#define NN     4096
#define DD     128
#define TPREV  2048
#define S1     8           // attn1 slices per batch (256 keys each)
#define S2     16          // attn2 slices per batch (256 keys each)
#define SL1    (TPREV/S1)  // 256
#define SL2    (NN/S2)     // 256
#define NW     8           // warps in slice kernels

// scratch (__device__ globals — no allocation)
__device__ float g_qkv[BB * 3 * DD];        // q,k,v per batch
__device__ float g_part[BB * S2 * 144];     // per-slice partials: m[8] l[8] O[128]
__device__ float g_ht1[BB * DD];
__device__ float g_q2[BB * DD];

__device__ __forceinline__ float warpReduceSum(float v) {
#pragma unroll
    for (int o = 16; o > 0; o >>= 1) v += __shfl_xor_sync(0xffffffffu, v, o);
    return v;
}

// out[j] = sum_i x[i]*W[j*128+i] + bias[j].  128 threads (4 warps x 32 rows).
__device__ void gemv128(const float* __restrict__ W, const float* __restrict__ bias,
                        const float* __restrict__ x, float* __restrict__ out, int tid)
{
    int warp = tid >> 5, lane = tid & 31;
    float4 xv = ((const float4*)x)[lane];
#pragma unroll 4
    for (int jj = 0; jj < 32; jj++) {
        int j = warp * 32 + jj;
        float4 wv = ((const float4*)(W + j * DD))[lane];
        float p = wv.x * xv.x + wv.y * xv.y + wv.z * xv.z + wv.w * xv.w;
        p = warpReduceSum(p);
        if (lane == 0) out[j] = p + bias[j];
    }
}

__device__ void layernorm128(float* __restrict__ x, const float* __restrict__ g,
                             const float* __restrict__ bb, int tid)
{
    if (tid < 32) {
        float v0 = x[tid], v1 = x[tid + 32], v2 = x[tid + 64], v3 = x[tid + 96];
        float s = warpReduceSum(v0 + v1 + v2 + v3);
        float mu = s * (1.0f / 128.0f);
        float d0 = v0 - mu, d1 = v1 - mu, d2 = v2 - mu, d3 = v3 - mu;
        float sq = warpReduceSum(d0 * d0 + d1 * d1 + d2 * d2 + d3 * d3);
        float rstd = rsqrtf(sq * (1.0f / 128.0f) + 1e-5f);
        x[tid]      = d0 * rstd * g[tid]      + bb[tid];
        x[tid + 32] = d1 * rstd * g[tid + 32] + bb[tid + 32];
        x[tid + 64] = d2 * rstd * g[tid + 64] + bb[tid + 64];
        x[tid + 96] = d3 * rstd * g[tid + 96] + bb[tid + 96];
    }
}

__device__ __forceinline__ void online_update(const float4& kk, const float4& vv,
                                              const float4& q4, float& m, float& l, float4& o)
{
    float s = kk.x * q4.x + kk.y * q4.y + kk.z * q4.z + kk.w * q4.w;
    s += __shfl_xor_sync(0xffffffffu, s, 1);
    s += __shfl_xor_sync(0xffffffffu, s, 2);
    s *= 0.25f;                               // 1/sqrt(dh=16)
    float mn = fmaxf(m, s);
    float sc = __expf(m - mn);
    float p  = __expf(s - mn);
    l = l * sc + p;
    o.x = o.x * sc + p * vv.x;
    o.y = o.y * sc + p * vv.y;
    o.z = o.z * sc + p * vv.z;
    o.w = o.w * sc + p * vv.w;
    m = mn;
}

// CTA merge of NW warp partials, store unnormalized (m,l,O) to gp[144].
__device__ void merge_store(float m, float l, float4 o, float* __restrict__ red,
                            float* __restrict__ gp, int tid)
{
    const int lane = tid & 31, warp = tid >> 5;
    float* red_o = red;
    float* red_m = red + NW * 128;
    float* red_l = red_m + NW * 8;

    ((float4*)(red_o + warp * 128))[lane] = o;
    if ((lane & 3) == 0) {
        red_m[warp * 8 + (lane >> 2)] = m;
        red_l[warp * 8 + (lane >> 2)] = l;
    }
    __syncthreads();

    if (tid < 128) {
        int hh = tid >> 4;
        float M = -INFINITY;
#pragma unroll
        for (int w = 0; w < NW; w++) M = fmaxf(M, red_m[w * 8 + hh]);
        float L = 0.f, O = 0.f;
#pragma unroll
        for (int w = 0; w < NW; w++) {
            float mw = red_m[w * 8 + hh];
            float sc = (mw > -INFINITY) ? __expf(mw - M) : 0.0f;
            L += red_l[w * 8 + hh] * sc;
            O += red_o[w * 128 + tid] * sc;
        }
        gp[16 + tid] = O;
        if ((tid & 15) == 0) { gp[hh] = M; gp[8 + hh] = L; }
    }
}

// ── K0: q/k/v projections ────────────────────────────────────────────────
__global__ void __launch_bounds__(128)
k0_qkv(const float* __restrict__ ht_in, const float* __restrict__ W,
       const float* __restrict__ bvec)
{
    const int b = blockIdx.x, tid = threadIdx.x;
    __shared__ float ht[128];
    ht[tid] = ht_in[(size_t)b * DD + tid];
    __syncthreads();
    float* qkv = g_qkv + (size_t)b * 3 * DD;
    gemv128(W + 0 * DD * DD, bvec + 0 * DD, ht, qkv,          tid);
    gemv128(W + 1 * DD * DD, bvec + 1 * DD, ht, qkv + DD,     tid);
    gemv128(W + 2 * DD * DD, bvec + 2 * DD, ht, qkv + 2 * DD, tid);
}

// ── K1: attn1 slice partials (unmasked) ──────────────────────────────────
__global__ void __launch_bounds__(256)
k1_attn1(const float* __restrict__ kprev, const float* __restrict__ vprev)
{
    const int b = blockIdx.x / S1, s = blockIdx.x % S1;
    const int tid = threadIdx.x, lane = tid & 31, warp = tid >> 5;
    __shared__ float red[NW * 128 + NW * 8 * 2];

    float4 q4 = ((const float4*)(g_qkv + (size_t)b * 3 * DD))[lane];
    const float4* Kb = (const float4*)kprev + ((size_t)b * TPREV + s * SL1) * 32;
    const float4* Vb = (const float4*)vprev + ((size_t)b * TPREV + s * SL1) * 32;

    float m = -INFINITY, l = 0.0f;
    float4 o = make_float4(0.f, 0.f, 0.f, 0.f);

    for (int t0 = warp; t0 < SL1; t0 += NW * 4) {
        float4 kk[4], vv[4];
#pragma unroll
        for (int u = 0; u < 4; u++) {
            int t = t0 + u * NW;
            kk[u] = Kb[(size_t)t * 32 + lane];
            vv[u] = Vb[(size_t)t * 32 + lane];
        }
#pragma unroll
        for (int u = 0; u < 4; u++) online_update(kk[u], vv[u], q4, m, l, o);
    }
    merge_store(m, l, o, red, g_part + ((size_t)b * S2 + s) * 144, tid);
}

// ── K2: combine attn1 + appended kv, glue, produce q2 ────────────────────
__global__ void __launch_bounds__(128)
k2_glue(const float* __restrict__ ht_in, const float* __restrict__ W,
        const float* __restrict__ bvec, const float* __restrict__ ln_g,
        const float* __restrict__ ln_b)
{
    const int b = blockIdx.x, tid = threadIdx.x;
    __shared__ float ht[128], att[128], tmp[128], qs[128], ks[128], vs[128];

    ht[tid] = ht_in[(size_t)b * DD + tid];
    const float* qkv = g_qkv + (size_t)b * 3 * DD;
    qs[tid] = qkv[tid]; ks[tid] = qkv[DD + tid]; vs[tid] = qkv[2 * DD + tid];
    __syncthreads();

    {
        int h = tid >> 4;
        // appended current-step key: analytic partial (m=s_ex, l=1, O=v)
        float s_ex = 0.f;
#pragma unroll
        for (int i = 0; i < 16; i++) s_ex += qs[h * 16 + i] * ks[h * 16 + i];
        s_ex *= 0.25f;

        const float* gp = g_part + (size_t)b * S2 * 144;
        float M = s_ex;
#pragma unroll
        for (int s = 0; s < S1; s++) M = fmaxf(M, gp[s * 144 + h]);
        float pe = __expf(s_ex - M);
        float L = pe, O = pe * vs[tid];
#pragma unroll
        for (int s = 0; s < S1; s++) {
            float mw = gp[s * 144 + h];
            float sc = (mw > -INFINITY) ? __expf(mw - M) : 0.0f;
            L += gp[s * 144 + 8 + h] * sc;
            O += gp[s * 144 + 16 + tid] * sc;
        }
        att[tid] = O / L;
    }
    __syncthreads();

    gemv128(W + 3 * DD * DD, bvec + 3 * DD, att, tmp, tid);
    __syncthreads();
    ht[tid] += tmp[tid];
    __syncthreads();
    layernorm128(ht, ln_g + 0 * DD, ln_b + 0 * DD, tid);
    __syncthreads();

    g_ht1[(size_t)b * DD + tid] = ht[tid];
    gemv128(W + 4 * DD * DD, bvec + 4 * DD, ht, g_q2 + (size_t)b * DD, tid);
}

// ── K3: attn2 slice partials (mask-skip) ─────────────────────────────────
__global__ void __launch_bounds__(256)
k3_attn2(const float* __restrict__ key, const float* __restrict__ value,
         const int* __restrict__ mask)
{
    const int b = blockIdx.x / S2, s = blockIdx.x % S2;
    const int tid = threadIdx.x, lane = tid & 31, warp = tid >> 5;
    __shared__ float red[NW * 128 + NW * 8 * 2];

    float4 q4 = ((const float4*)(g_q2 + (size_t)b * DD))[lane];
    const float4* Kb = (const float4*)key   + (size_t)b * NN * 32;
    const float4* Vb = (const float4*)value + (size_t)b * NN * 32;

    // warp w owns 32 contiguous keys
    const int base = s * SL2 + warp * 32;
    unsigned word = __ballot_sync(0xffffffffu, mask[(size_t)b * NN + base + lane] == 1);

    float m = -INFINITY, l = 0.0f;
    float4 o = make_float4(0.f, 0.f, 0.f, 0.f);

    if (word != 0xffffffffu) {
#pragma unroll
        for (int j0 = 0; j0 < 32; j0 += 4) {
            float4 kk[4], vv[4];
            bool act[4];
#pragma unroll
            for (int u = 0; u < 4; u++) {
                act[u] = ((word >> (j0 + u)) & 1u) == 0u;
                if (act[u]) {
                    int t = base + j0 + u;
                    kk[u] = Kb[(size_t)t * 32 + lane];
                    vv[u] = Vb[(size_t)t * 32 + lane];
                }
            }
#pragma unroll
            for (int u = 0; u < 4; u++)
                if (act[u]) online_update(kk[u], vv[u], q4, m, l, o);
        }
    }
    merge_store(m, l, o, red, g_part + ((size_t)b * S2 + s) * 144, tid);
}

// ── K4: combine attn2, glue, FFN, output ─────────────────────────────────
__global__ void __launch_bounds__(128)
k4_out(const float* __restrict__ W, const float* __restrict__ bvec,
       const float* __restrict__ ln_g, const float* __restrict__ ln_b,
       float* __restrict__ out)
{
    const int b = blockIdx.x, tid = threadIdx.x;
    __shared__ float ht[128], att[128], tmp[128];

    ht[tid] = g_ht1[(size_t)b * DD + tid];

    {
        int h = tid >> 4;
        const float* gp = g_part + (size_t)b * S2 * 144;
        float M = -INFINITY;
#pragma unroll
        for (int s = 0; s < S2; s++) M = fmaxf(M, gp[s * 144 + h]);
        float L = 0.f, O = 0.f;
#pragma unroll
        for (int s = 0; s < S2; s++) {
            float mw = gp[s * 144 + h];
            float sc = (mw > -INFINITY) ? __expf(mw - M) : 0.0f;
            L += gp[s * 144 + 8 + h] * sc;
            O += gp[s * 144 + 16 + tid] * sc;
        }
        att[tid] = O / L;
    }
    __syncthreads();

    gemv128(W + 5 * DD * DD, bvec + 5 * DD, att, tmp, tid);
    __syncthreads();
    ht[tid] += tmp[tid];
    __syncthreads();
    layernorm128(ht, ln_g + 1 * DD, ln_b + 1 * DD, tid);
    __syncthreads();

    gemv128(W + 7 * DD * DD, bvec + 7 * DD, ht, tmp, tid);
    __syncthreads();
    tmp[tid] = fmaxf(tmp[tid], 0.0f);
    __syncthreads();
    gemv128(W + 6 * DD * DD, bvec + 6 * DD, tmp, att, tid);
    __syncthreads();
    ht[tid] += att[tid];
    __syncthreads();
    layernorm128(ht, ln_g + 2 * DD, ln_b + 2 * DD, tid);
    __syncthreads();

    out[(size_t)b * DD + tid] = ht[tid];
}

extern "C" void kernel_launch(void* const* d_in, const int* in_sizes, int n_in,
                              void* d_out, int out_size)
{
    const float* ht    = (const float*)d_in[0];
    const float* key   = (const float*)d_in[1];
    const float* value = (const float*)d_in[2];
    const int*   mask  = (const int*)  d_in[3];
    const float* kprev = (const float*)d_in[4];
    const float* vprev = (const float*)d_in[5];
    const float* W     = (const float*)d_in[6];
    const float* bvec  = (const float*)d_in[7];
    const float* ln_g  = (const float*)d_in[8];
    const float* ln_b  = (const float*)d_in[9];
    float* out = (float*)d_out;

    k0_qkv  <<<BB,      128>>>(ht, W, bvec);
    k1_attn1<<<BB * S1, 256>>>(kprev, vprev);
    k2_glue <<<BB,      128>>>(ht, W, bvec, ln_g, ln_b);
    k3_attn2<<<BB * S2, 256>>>(key, value, mask);
    k4_out  <<<BB,      128>>>(W, bvec, ln_g, ln_b, out);
}

// round 10
// speedup vs baseline: 1.2425x; 1.2425x over previous
#include <cuda_runtime.h>
#include <math.h>
#include <stdint.h>

#define BB     512
#define NN     4096
#define DD     128
#define HH     8
#define TPREV  2048
#define NW     8       // warps per CTA
#define NT     256
#define PERW   (NN / NW)   // 512 keys per warp in attn2

__device__ __forceinline__ float warpReduceSum(float v) {
#pragma unroll
    for (int o = 16; o > 0; o >>= 1) v += __shfl_xor_sync(0xffffffffu, v, o);
    return v;
}

// out[j] = sum_i x[i]*W[j*128+i] + bias[j]. All 256 threads.
__device__ void gemv128(const float* __restrict__ W, const float* __restrict__ bias,
                        const float* __restrict__ x, float* __restrict__ out, int tid)
{
    int warp = tid >> 5, lane = tid & 31;
    float4 xv = ((const float4*)x)[lane];
#pragma unroll
    for (int jj = 0; jj < 16; jj++) {
        int j = warp * 16 + jj;
        float4 wv = ((const float4*)(W + j * DD))[lane];
        float p = wv.x * xv.x + wv.y * xv.y + wv.z * xv.z + wv.w * xv.w;
        p = warpReduceSum(p);
        if (lane == 0) out[j] = p + bias[j];
    }
}

__device__ void layernorm128(float* __restrict__ x, const float* __restrict__ g,
                             const float* __restrict__ bb, int tid)
{
    if (tid < 32) {
        float v0 = x[tid], v1 = x[tid + 32], v2 = x[tid + 64], v3 = x[tid + 96];
        float s = warpReduceSum(v0 + v1 + v2 + v3);
        float mu = s * (1.0f / 128.0f);
        float d0 = v0 - mu, d1 = v1 - mu, d2 = v2 - mu, d3 = v3 - mu;
        float sq = warpReduceSum(d0 * d0 + d1 * d1 + d2 * d2 + d3 * d3);
        float rstd = rsqrtf(sq * (1.0f / 128.0f) + 1e-5f);
        x[tid]      = d0 * rstd * g[tid]      + bb[tid];
        x[tid + 32] = d1 * rstd * g[tid + 32] + bb[tid + 32];
        x[tid + 64] = d2 * rstd * g[tid + 64] + bb[tid + 64];
        x[tid + 96] = d3 * rstd * g[tid + 96] + bb[tid + 96];
    }
}

__device__ __forceinline__ void online_update(const float4& kk, const float4& vv,
                                              const float4& q4, float& m, float& l,
                                              float4& o)
{
    float s = kk.x * q4.x + kk.y * q4.y + kk.z * q4.z + kk.w * q4.w;
    s += __shfl_xor_sync(0xffffffffu, s, 1);
    s += __shfl_xor_sync(0xffffffffu, s, 2);
    s *= 0.25f;                               // 1/sqrt(dh=16)
    float mn = fmaxf(m, s);
    float sc = __expf(m - mn);
    float p  = __expf(s - mn);
    l = l * sc + p;
    o.x = o.x * sc + p * vv.x;
    o.y = o.y * sc + p * vv.y;
    o.z = o.z * sc + p * vv.z;
    o.w = o.w * sc + p * vv.w;
    m = mn;
}

// Cross-warp merge of online-softmax partials. red layout: [NW*128] o, [NW*8] m, [NW*8] l.
__device__ void merge_partials(float m, float l, float4 o, float* __restrict__ red,
                               float* __restrict__ out, int tid)
{
    const int lane = tid & 31, warp = tid >> 5;
    float* red_o = red;
    float* red_m = red + NW * 128;
    float* red_l = red_m + NW * 8;

    ((float4*)(red_o + warp * 128))[lane] = o;
    if ((lane & 3) == 0) {
        red_m[warp * 8 + (lane >> 2)] = m;
        red_l[warp * 8 + (lane >> 2)] = l;
    }
    __syncthreads();

    if (tid < 128) {
        int hh = tid >> 4;
        float M = -INFINITY;
#pragma unroll
        for (int w = 0; w < NW; w++) M = fmaxf(M, red_m[w * 8 + hh]);
        float L = 0.f, O = 0.f;
#pragma unroll
        for (int w = 0; w < NW; w++) {
            float mw = red_m[w * 8 + hh];
            float sc = (mw > -INFINITY) ? __expf(mw - M) : 0.0f;
            L += red_l[w * 8 + hh] * sc;
            O += red_o[w * 128 + tid] * sc;
        }
        out[tid] = O / L;
    }
    __syncthreads();
}

// Attention 1: unmasked stream over nkeys, plus one extra appended K/V from smem.
__device__ void attention_plain(const float4* __restrict__ Kb, const float4* __restrict__ Vb,
                                int nkeys, const float* __restrict__ q,
                                const float* __restrict__ kex, const float* __restrict__ vex,
                                float* __restrict__ out, float* __restrict__ red, int tid)
{
    const int lane = tid & 31, warp = tid >> 5;
    float4 q4 = ((const float4*)q)[lane];
    float m = -INFINITY, l = 0.0f;
    float4 o = make_float4(0.f, 0.f, 0.f, 0.f);

    for (int t0 = warp; t0 < nkeys; t0 += NW * 4) {
        float4 kk[4], vv[4];
#pragma unroll
        for (int u = 0; u < 4; u++) {
            int t = t0 + u * NW;
            kk[u] = Kb[(size_t)t * 32 + lane];
            vv[u] = Vb[(size_t)t * 32 + lane];
        }
#pragma unroll
        for (int u = 0; u < 4; u++) online_update(kk[u], vv[u], q4, m, l, o);
    }

    if (warp == 0) {  // appended current-step k/v
        float4 kk = ((const float4*)kex)[lane];
        float4 vv = ((const float4*)vex)[lane];
        online_update(kk, vv, q4, m, l, o);
    }
    merge_partials(m, l, o, red, out, tid);
}

// Attention 2: dense walk over precompacted active-key index list (idxl[warp*PERW..])
// cnt = number of active keys for this warp. Every load is unconditional -> MLP 8.
__device__ void attention_compact(const float4* __restrict__ Kb, const float4* __restrict__ Vb,
                                  const int* __restrict__ idxl, int cnt,
                                  const float* __restrict__ q,
                                  float* __restrict__ out, float* __restrict__ red, int tid)
{
    const int lane = tid & 31, warp = tid >> 5;
    float4 q4 = ((const float4*)q)[lane];
    float m = -INFINITY, l = 0.0f;
    float4 o = make_float4(0.f, 0.f, 0.f, 0.f);

    const int* wl = idxl + warp * PERW;
    int i = 0;
    for (; i + 4 <= cnt; i += 4) {
        int4 t4 = *(const int4*)(wl + i);     // smem broadcast, 16B aligned
        float4 kk[4], vv[4];
        kk[0] = Kb[(size_t)t4.x * 32 + lane];
        vv[0] = Vb[(size_t)t4.x * 32 + lane];
        kk[1] = Kb[(size_t)t4.y * 32 + lane];
        vv[1] = Vb[(size_t)t4.y * 32 + lane];
        kk[2] = Kb[(size_t)t4.z * 32 + lane];
        vv[2] = Vb[(size_t)t4.z * 32 + lane];
        kk[3] = Kb[(size_t)t4.w * 32 + lane];
        vv[3] = Vb[(size_t)t4.w * 32 + lane];
#pragma unroll
        for (int u = 0; u < 4; u++) online_update(kk[u], vv[u], q4, m, l, o);
    }
    for (; i < cnt; i++) {
        int t = wl[i];
        float4 kk = Kb[(size_t)t * 32 + lane];
        float4 vv = Vb[(size_t)t * 32 + lane];
        online_update(kk, vv, q4, m, l, o);
    }
    merge_partials(m, l, o, red, out, tid);
}

__global__ void __launch_bounds__(NT, 4)
ARD_67765993997201_kernel(const float* __restrict__ ht_in,
                          const float* __restrict__ key,
                          const float* __restrict__ value,
                          const int*   __restrict__ mask,
                          const float* __restrict__ kprev,
                          const float* __restrict__ vprev,
                          const float* __restrict__ W,
                          const float* __restrict__ bvec,
                          const float* __restrict__ ln_g,
                          const float* __restrict__ ln_b,
                          float* __restrict__ out)
{
    const int b = blockIdx.x;
    const int tid = threadIdx.x;
    const int lane = tid & 31, warp = tid >> 5;

    __shared__ float ht[128], qb[128], kb[128], vb[128], tmp[128], att[128];
    __shared__ float red[NW * 128 + NW * 8 * 2];
    __shared__ int idxl[NN];                 // 16 KB: compacted active key indices
    __shared__ int wcnt[NW];

    if (tid < 128) ht[tid] = ht_in[(size_t)b * DD + tid];

    // Compact this warp's 512-key mask range into a dense index list.
    // Warp w owns keys [w*512, (w+1)*512).
    {
        const int* mb = mask + (size_t)b * NN;
        const int start = warp * PERW;
        int cnt = 0;
        int* wl = idxl + warp * PERW;
#pragma unroll
        for (int r = 0; r < PERW / 32; r++) {        // 16 words
            int t = start + r * 32 + lane;
            unsigned word = __ballot_sync(0xffffffffu, mb[t] == 1);  // masked bits
            unsigned act = ~word;
            if ((act >> lane) & 1u) {
                int pfx = __popc(act & ((1u << lane) - 1u));
                wl[cnt + pfx] = t;
            }
            cnt += __popc(act);
        }
        if (lane == 0) wcnt[warp] = cnt;
    }
    __syncthreads();

    // q, k, v projections
    gemv128(W + 0 * DD * DD, bvec + 0 * DD, ht, qb, tid);
    gemv128(W + 1 * DD * DD, bvec + 1 * DD, ht, kb, tid);
    gemv128(W + 2 * DD * DD, bvec + 2 * DD, ht, vb, tid);
    __syncthreads();

    // Attention 1: over [kprev ; k], [vprev ; v], no mask
    attention_plain((const float4*)kprev + (size_t)b * TPREV * 32,
                    (const float4*)vprev + (size_t)b * TPREV * 32,
                    TPREV, qb, kb, vb, att, red, tid);

    gemv128(W + 3 * DD * DD, bvec + 3 * DD, att, tmp, tid);
    __syncthreads();
    if (tid < 128) ht[tid] += tmp[tid];
    __syncthreads();
    layernorm128(ht, ln_g + 0 * DD, ln_b + 0 * DD, tid);
    __syncthreads();

    // query projection
    gemv128(W + 4 * DD * DD, bvec + 4 * DD, ht, qb, tid);
    __syncthreads();

    // Attention 2: dense compacted walk over active keys
    attention_compact((const float4*)key   + (size_t)b * NN * 32,
                      (const float4*)value + (size_t)b * NN * 32,
                      idxl, wcnt[warp], qb, att, red, tid);

    gemv128(W + 5 * DD * DD, bvec + 5 * DD, att, tmp, tid);
    __syncthreads();
    if (tid < 128) ht[tid] += tmp[tid];
    __syncthreads();
    layernorm128(ht, ln_g + 1 * DD, ln_b + 1 * DD, tid);
    __syncthreads();

    // FFN: ht += W6 @ relu(W7 @ ht + b7) + b6
    gemv128(W + 7 * DD * DD, bvec + 7 * DD, ht, tmp, tid);
    __syncthreads();
    if (tid < 128) tmp[tid] = fmaxf(tmp[tid], 0.0f);
    __syncthreads();
    gemv128(W + 6 * DD * DD, bvec + 6 * DD, tmp, qb, tid);
    __syncthreads();
    if (tid < 128) ht[tid] += qb[tid];
    __syncthreads();
    layernorm128(ht, ln_g + 2 * DD, ln_b + 2 * DD, tid);
    __syncthreads();

    if (tid < 128) out[(size_t)b * DD + tid] = ht[tid];
}

extern "C" void kernel_launch(void* const* d_in, const int* in_sizes, int n_in,
                              void* d_out, int out_size)
{
    const float* ht    = (const float*)d_in[0];
    const float* key   = (const float*)d_in[1];
    const float* value = (const float*)d_in[2];
    const int*   mask  = (const int*)  d_in[3];
    const float* kprev = (const float*)d_in[4];
    const float* vprev = (const float*)d_in[5];
    const float* W     = (const float*)d_in[6];
    const float* bvec  = (const float*)d_in[7];
    const float* ln_g  = (const float*)d_in[8];
    const float* ln_b  = (const float*)d_in[9];
    float* out = (float*)d_out;

    ARD_67765993997201_kernel<<<BB, NT>>>(ht, key, value, mask, kprev, vprev,
                                          W, bvec, ln_g, ln_b, out);
}